// round 1
// baseline (speedup 1.0000x reference)
#include <cuda_runtime.h>
#include <math.h>

// Problem constants (fixed by the reference).
#define B_ 2
#define S_ 2048
#define D_ 1024
#define H_ 16
#define DK_ 64
#define M_ (B_ * S_)   // 4096 rows in the "token" dimension

// Scratch (allocation-free rule: __device__ globals).
__device__ float g_q[B_ * H_ * S_ * DK_];     // [b,h,s,d]
__device__ float g_k[B_ * H_ * S_ * DK_];
__device__ float g_v[B_ * H_ * S_ * DK_];
__device__ float g_attn[M_ * D_];             // [b,s,h*dk]  (token-major for final GEMM)

// ---------------------------------------------------------------------------
// GEMM (NT): C[m,n] = sum_k A[m,k] * W[n,k].  A: [M,1024] row-major,
// W: [1024,1024] row-major (each row is a length-1024 K vector).
// 128x128 tile, BK=32, 256 threads, 8x8 microtile.
// MODE 0: plain write C[m*1024 + n]  (final output projection)
// MODE 1: scatter into [b,h,s,d] layout (q/k/v projections)
// ---------------------------------------------------------------------------
template <int MODE>
__global__ void __launch_bounds__(256) gemm_nt_kernel(const float* __restrict__ A,
                                                      const float* __restrict__ W,
                                                      float* __restrict__ Cout) {
    __shared__ float As[32][128];
    __shared__ float Bs[32][128];

    const int tid = threadIdx.x;
    const int tx = tid & 15;
    const int ty = tid >> 4;
    const int m0 = blockIdx.y * 128;
    const int n0 = blockIdx.x * 128;

    const float* Ab = A + (size_t)m0 * D_;
    const float* Wb = W + (size_t)n0 * D_;

    float acc[8][8];
#pragma unroll
    for (int i = 0; i < 8; ++i)
#pragma unroll
        for (int j = 0; j < 8; ++j) acc[i][j] = 0.0f;

    for (int k0 = 0; k0 < D_; k0 += 32) {
        // Cooperative load: 128 rows x 32 cols each for A and W, stored
        // transposed (K-major) into smem.
#pragma unroll
        for (int i = 0; i < 4; ++i) {
            int l = tid + i * 256;
            int r = l >> 3;              // 0..127
            int c = (l & 7) << 2;        // 0,4,...,28
            float4 a4 = *reinterpret_cast<const float4*>(Ab + (size_t)r * D_ + k0 + c);
            As[c + 0][r] = a4.x; As[c + 1][r] = a4.y;
            As[c + 2][r] = a4.z; As[c + 3][r] = a4.w;
            float4 b4 = *reinterpret_cast<const float4*>(Wb + (size_t)r * D_ + k0 + c);
            Bs[c + 0][r] = b4.x; Bs[c + 1][r] = b4.y;
            Bs[c + 2][r] = b4.z; Bs[c + 3][r] = b4.w;
        }
        __syncthreads();

#pragma unroll 8
        for (int kk = 0; kk < 32; ++kk) {
            float a[8], b[8];
            *reinterpret_cast<float4*>(&a[0]) =
                *reinterpret_cast<const float4*>(&As[kk][ty * 8]);
            *reinterpret_cast<float4*>(&a[4]) =
                *reinterpret_cast<const float4*>(&As[kk][ty * 8 + 4]);
            *reinterpret_cast<float4*>(&b[0]) =
                *reinterpret_cast<const float4*>(&Bs[kk][tx * 8]);
            *reinterpret_cast<float4*>(&b[4]) =
                *reinterpret_cast<const float4*>(&Bs[kk][tx * 8 + 4]);
#pragma unroll
            for (int i = 0; i < 8; ++i)
#pragma unroll
                for (int j = 0; j < 8; ++j) acc[i][j] = fmaf(a[i], b[j], acc[i][j]);
        }
        __syncthreads();
    }

    // Epilogue
#pragma unroll
    for (int i = 0; i < 8; ++i) {
        int m = m0 + ty * 8 + i;
        float4 lo = make_float4(acc[i][0], acc[i][1], acc[i][2], acc[i][3]);
        float4 hi = make_float4(acc[i][4], acc[i][5], acc[i][6], acc[i][7]);
        if (MODE == 0) {
            float* o = Cout + (size_t)m * D_ + n0 + tx * 8;
            *reinterpret_cast<float4*>(o + 0) = lo;
            *reinterpret_cast<float4*>(o + 4) = hi;
        } else {
            int b = m >> 11;           // m / 2048
            int s = m & (S_ - 1);
            int n = n0 + tx * 8;       // multiple of 8; stays within one head (dk=64)
            int h = n >> 6;
            int d = n & 63;
            float* o = Cout + (((size_t)(b * H_ + h) * S_ + s) * DK_ + d);
            *reinterpret_cast<float4*>(o + 0) = lo;
            *reinterpret_cast<float4*>(o + 4) = hi;
        }
    }
}

// ---------------------------------------------------------------------------
// RoPE over q and k in-place, [b,h,s,d] layout. One thread per (pair).
// Interleaved pairs: out[2j] = e*cos - o*sin ; out[2j+1] = e*sin + o*cos.
// ---------------------------------------------------------------------------
__global__ void rope_kernel(const int* __restrict__ pos) {
    const int NP = B_ * H_ * S_ * (DK_ / 2);   // pairs per tensor
    int t = blockIdx.x * blockDim.x + threadIdx.x;
    if (t >= 2 * NP) return;
    float* base = (t < NP) ? g_q : g_k;
    int u = (t < NP) ? t : t - NP;

    int j = u & 31;                 // pair index 0..31
    int s = (u >> 5) & (S_ - 1);
    int bh = u >> 16;               // (32 pairs * 2048 s) = 2^16 per (b,h)
    int b = bh >> 4;

    float p = (float)pos[b * S_ + s];
    float freq = powf(10000.0f, -((float)(2 * j) / 64.0f));
    float ang = p * freq;
    float c = (float)cos((double)ang);
    float sn = (float)sin((double)ang);

    float* ptr = base + ((size_t)bh * S_ + s) * DK_ + 2 * j;
    float2 eo = *reinterpret_cast<float2*>(ptr);
    float2 r;
    r.x = eo.x * c - eo.y * sn;
    r.y = eo.x * sn + eo.y * c;
    *reinterpret_cast<float2*>(ptr) = r;
}

// ---------------------------------------------------------------------------
// Flash attention, fp32, causal. 64 q-rows per block, k in 64-row tiles.
// 256 threads = 16x16; each thread owns a 4x4 microtile of S and of O.
// Smem (dynamic, stride-68 rows to kill bank conflicts):
//   Qts[64][68]  Q^T tile  ([kk][row]), pre-scaled by 1/sqrt(dk)
//   KPs[64][68]  K^T tile  ([kk][col]) then reused for P ([row][kk])
//   Vs [64][68]  V tile    ([kk][col])
// ---------------------------------------------------------------------------
#define FLASH_SMEM (3 * 64 * 68 * 4)

__global__ void __launch_bounds__(256) flash_kernel() {
    extern __shared__ float sm[];
    float (*Qts)[68] = reinterpret_cast<float (*)[68]>(sm);
    float (*KPs)[68] = reinterpret_cast<float (*)[68]>(sm + 64 * 68);
    float (*Vs)[68]  = reinterpret_cast<float (*)[68]>(sm + 2 * 64 * 68);

    const int qb = blockIdx.x;          // 0..31
    const int bh = blockIdx.y;          // 0..31
    const int b = bh >> 4;
    const int h = bh & 15;

    const float* Qp = g_q + (size_t)bh * S_ * DK_;
    const float* Kp = g_k + (size_t)bh * S_ * DK_;
    const float* Vp = g_v + (size_t)bh * S_ * DK_;

    const int tid = threadIdx.x;
    const int tx = tid & 15;
    const int ty = tid >> 4;
    const int q0 = qb * 64;
    const float scale = 0.125f;   // 1/sqrt(64)

    // Load Q tile transposed into Qts[kk][row], scaled.
#pragma unroll
    for (int i = 0; i < 4; ++i) {
        int l = tid + i * 256;
        int r = l >> 4;              // 0..63
        int c = (l & 15) << 2;       // 0,4,...,60
        float4 v = *reinterpret_cast<const float4*>(Qp + (size_t)(q0 + r) * DK_ + c);
        Qts[c + 0][r] = v.x * scale;
        Qts[c + 1][r] = v.y * scale;
        Qts[c + 2][r] = v.z * scale;
        Qts[c + 3][r] = v.w * scale;
    }

    float m_i[4] = {-1e30f, -1e30f, -1e30f, -1e30f};
    float l_i[4] = {0.f, 0.f, 0.f, 0.f};
    float Oa[4][4];
#pragma unroll
    for (int i = 0; i < 4; ++i)
#pragma unroll
        for (int j = 0; j < 4; ++j) Oa[i][j] = 0.0f;

    for (int kb = 0; kb <= qb; ++kb) {
        const int k0 = kb * 64;
        __syncthreads();   // previous iteration's reads done (and Q visible, 1st iter)

        // Load K (transposed) and V tiles.
#pragma unroll
        for (int i = 0; i < 4; ++i) {
            int l = tid + i * 256;
            int r = l >> 4;
            int c = (l & 15) << 2;
            float4 kv = *reinterpret_cast<const float4*>(Kp + (size_t)(k0 + r) * DK_ + c);
            KPs[c + 0][r] = kv.x; KPs[c + 1][r] = kv.y;
            KPs[c + 2][r] = kv.z; KPs[c + 3][r] = kv.w;
            float4 vv = *reinterpret_cast<const float4*>(Vp + (size_t)(k0 + r) * DK_ + c);
            *reinterpret_cast<float4*>(&Vs[r][c]) = vv;
        }
        __syncthreads();

        // S = Q K^T  (this thread: rows ty*4+i, cols tx*4+j)
        float sf[4][4];
#pragma unroll
        for (int i = 0; i < 4; ++i)
#pragma unroll
            for (int j = 0; j < 4; ++j) sf[i][j] = 0.0f;

#pragma unroll 8
        for (int kk = 0; kk < 64; ++kk) {
            float4 a4 = *reinterpret_cast<const float4*>(&Qts[kk][ty * 4]);
            float4 b4 = *reinterpret_cast<const float4*>(&KPs[kk][tx * 4]);
            float qv[4] = {a4.x, a4.y, a4.z, a4.w};
            float kv[4] = {b4.x, b4.y, b4.z, b4.w};
#pragma unroll
            for (int i = 0; i < 4; ++i)
#pragma unroll
                for (int j = 0; j < 4; ++j) sf[i][j] = fmaf(qv[i], kv[j], sf[i][j]);
        }

        // Causal mask on the diagonal block (k0 == q0 there).
        if (kb == qb) {
#pragma unroll
            for (int i = 0; i < 4; ++i)
#pragma unroll
                for (int j = 0; j < 4; ++j)
                    if (tx * 4 + j > ty * 4 + i) sf[i][j] = -1e30f;
        }

        // Online softmax update per row.
#pragma unroll
        for (int i = 0; i < 4; ++i) {
            float mx = fmaxf(fmaxf(sf[i][0], sf[i][1]), fmaxf(sf[i][2], sf[i][3]));
#pragma unroll
            for (int off = 8; off > 0; off >>= 1)
                mx = fmaxf(mx, __shfl_xor_sync(0xffffffffu, mx, off));
            float mn = fmaxf(m_i[i], mx);
            float alpha = expf(m_i[i] - mn);
            float ps = 0.0f;
#pragma unroll
            for (int j = 0; j < 4; ++j) {
                float pp = expf(sf[i][j] - mn);
                sf[i][j] = pp;
                ps += pp;
            }
#pragma unroll
            for (int off = 8; off > 0; off >>= 1)
                ps += __shfl_xor_sync(0xffffffffu, ps, off);
            l_i[i] = l_i[i] * alpha + ps;
            m_i[i] = mn;
#pragma unroll
            for (int j = 0; j < 4; ++j) Oa[i][j] *= alpha;
        }

        __syncthreads();   // everyone done reading KPs as K^T
        // Write P into KPs ([row][kk] layout).
#pragma unroll
        for (int i = 0; i < 4; ++i)
            *reinterpret_cast<float4*>(&KPs[ty * 4 + i][tx * 4]) =
                make_float4(sf[i][0], sf[i][1], sf[i][2], sf[i][3]);
        __syncthreads();

        // O += P @ V
#pragma unroll 8
        for (int kk = 0; kk < 64; ++kk) {
            float4 b4 = *reinterpret_cast<const float4*>(&Vs[kk][tx * 4]);
            float vv[4] = {b4.x, b4.y, b4.z, b4.w};
            float pv[4];
#pragma unroll
            for (int i = 0; i < 4; ++i) pv[i] = KPs[ty * 4 + i][kk];
#pragma unroll
            for (int i = 0; i < 4; ++i)
#pragma unroll
                for (int j = 0; j < 4; ++j) Oa[i][j] = fmaf(pv[i], vv[j], Oa[i][j]);
        }
    }

    // Normalize and write to [b, s, h*64+d] token-major layout.
#pragma unroll
    for (int i = 0; i < 4; ++i) {
        float inv = 1.0f / l_i[i];
        int r = q0 + ty * 4 + i;
        float4 o = make_float4(Oa[i][0] * inv, Oa[i][1] * inv,
                               Oa[i][2] * inv, Oa[i][3] * inv);
        *reinterpret_cast<float4*>(
            &g_attn[((size_t)(b * S_ + r)) * D_ + h * DK_ + tx * 4]) = o;
    }
}

// ---------------------------------------------------------------------------
extern "C" void kernel_launch(void* const* d_in, const int* in_sizes, int n_in,
                              void* d_out, int out_size) {
    const float* x  = (const float*)d_in[0];
    const int* pos  = (const int*)d_in[1];
    const float* wq = (const float*)d_in[2];
    const float* wk = (const float*)d_in[3];
    const float* wv = (const float*)d_in[4];
    const float* wo = (const float*)d_in[5];
    float* out = (float*)d_out;

    float *qp, *kp, *vp, *attnp;
    cudaGetSymbolAddress((void**)&qp, g_q);
    cudaGetSymbolAddress((void**)&kp, g_k);
    cudaGetSymbolAddress((void**)&vp, g_v);
    cudaGetSymbolAddress((void**)&attnp, g_attn);

    cudaFuncSetAttribute(flash_kernel,
                         cudaFuncAttributeMaxDynamicSharedMemorySize, FLASH_SMEM);

    dim3 gemm_grid(D_ / 128, M_ / 128);   // (8, 32)
    gemm_nt_kernel<1><<<gemm_grid, 256>>>(x, wq, qp);
    gemm_nt_kernel<1><<<gemm_grid, 256>>>(x, wk, kp);
    gemm_nt_kernel<1><<<gemm_grid, 256>>>(x, wv, vp);

    int rope_total = 2 * B_ * H_ * S_ * (DK_ / 2);
    rope_kernel<<<rope_total / 256, 256>>>(pos);

    dim3 flash_grid(S_ / 64, B_ * H_);    // (32, 32)
    flash_kernel<<<flash_grid, 256, FLASH_SMEM>>>();

    gemm_nt_kernel<0><<<gemm_grid, 256>>>(attnp, wo, out);
}

// round 2
// speedup vs baseline: 1.7085x; 1.7085x over previous
#include <cuda_runtime.h>
#include <math.h>

// Problem constants (fixed by the reference).
#define B_ 2
#define S_ 2048
#define D_ 1024
#define H_ 16
#define DK_ 64
#define M_ (B_ * S_)   // 4096 token rows

// Scratch (allocation-free rule: __device__ globals).
__device__ float g_q[B_ * H_ * S_ * DK_];     // [b,h,s,d]
__device__ float g_k[B_ * H_ * S_ * DK_];
__device__ float g_v[B_ * H_ * S_ * DK_];
__device__ float g_attn[M_ * D_];             // [b,s,h*dk]

// ---------------------------------------------------------------------------
// tf32 helpers
// ---------------------------------------------------------------------------
__device__ __forceinline__ unsigned f2tf32(float f) {
    unsigned u;
    asm("cvt.rna.tf32.f32 %0, %1;" : "=r"(u) : "f"(f));
    return u;
}

__device__ __forceinline__ void mma_tf32(float (&c)[4], const unsigned (&a)[4],
                                         const unsigned (&b)[2]) {
    asm volatile(
        "mma.sync.aligned.m16n8k8.row.col.f32.tf32.tf32.f32 "
        "{%0,%1,%2,%3}, {%4,%5,%6,%7}, {%8,%9}, {%0,%1,%2,%3};\n"
        : "+f"(c[0]), "+f"(c[1]), "+f"(c[2]), "+f"(c[3])
        : "r"(a[0]), "r"(a[1]), "r"(a[2]), "r"(a[3]), "r"(b[0]), "r"(b[1]));
}

__device__ __forceinline__ void cp_async16(void* smem, const void* gmem) {
    unsigned saddr = (unsigned)__cvta_generic_to_shared(smem);
    asm volatile("cp.async.cg.shared.global [%0], [%1], 16;\n" ::"r"(saddr),
                 "l"(gmem));
}
__device__ __forceinline__ void cp_commit() {
    asm volatile("cp.async.commit_group;\n");
}
template <int N>
__device__ __forceinline__ void cp_wait() {
    asm volatile("cp.async.wait_group %0;\n" ::"n"(N));
}

// ---------------------------------------------------------------------------
// tf32 GEMM (NT): C[m,n] = sum_k A[m,k] * W[n,k].
// A: [4096,1024] row-major. W: [1024,1024] row-major (rows = output features).
// Tile 128x128, BK=32, 256 threads, 8 warps (2 m x 4 n), warp tile 64x32.
// MODE 0: C[m*1024+n] plain                 (output projection)
// MODE 1: scatter to [b,h,s,d]              (v projection)
// MODE 2: scatter to [b,h,s,d] + fused RoPE (q,k projections)
// Dynamic smem: As[2][128][36], Bs[2][128][36]  (pad 4 -> conflict-free frags)
// ---------------------------------------------------------------------------
#define GSTRIDE 36
#define GEMM_SMEM (2 * 2 * 128 * GSTRIDE * 4)

template <int MODE>
__global__ void __launch_bounds__(256) gemm_tf32_kernel(
    const float* __restrict__ A, const float* __restrict__ W,
    float* __restrict__ Cout, const int* __restrict__ pos) {
    extern __shared__ float sm[];
    float(*As)[128][GSTRIDE] = reinterpret_cast<float(*)[128][GSTRIDE]>(sm);
    float(*Bs)[128][GSTRIDE] =
        reinterpret_cast<float(*)[128][GSTRIDE]>(sm + 2 * 128 * GSTRIDE);

    const int tid = threadIdx.x;
    const int lane = tid & 31;
    const int warp = tid >> 5;
    const int wr = warp >> 2;         // 0..1 -> 64-row slab
    const int wc = warp & 3;          // 0..3 -> 32-col slab
    const int m0 = blockIdx.y * 128;
    const int n0 = blockIdx.x * 128;
    const int gid = lane >> 2;        // groupID
    const int tig = lane & 3;         // threadID_in_group

    const float* Ab = A + (size_t)m0 * D_;
    const float* Wb = W + (size_t)n0 * D_;

    float acc[4][4][4];
#pragma unroll
    for (int i = 0; i < 4; ++i)
#pragma unroll
        for (int j = 0; j < 4; ++j)
#pragma unroll
            for (int r = 0; r < 4; ++r) acc[i][j][r] = 0.0f;

    // Issue async copy of one 128x32 K-slab of A and W into buffer `buf`.
    auto issue = [&](int buf, int k0) {
#pragma unroll
        for (int i = 0; i < 4; ++i) {
            int l = tid + i * 256;
            int r = l >> 3;
            int c = (l & 7) << 2;
            cp_async16(&As[buf][r][c], Ab + (size_t)r * D_ + k0 + c);
            cp_async16(&Bs[buf][r][c], Wb + (size_t)r * D_ + k0 + c);
        }
        cp_commit();
    };

    const int NIT = D_ / 32;
    issue(0, 0);
    int buf = 0;
    for (int it = 0; it < NIT; ++it) {
        if (it + 1 < NIT) {
            issue(buf ^ 1, (it + 1) * 32);
            cp_wait<1>();
        } else {
            cp_wait<0>();
        }
        __syncthreads();

#pragma unroll
        for (int kk = 0; kk < 32; kk += 8) {
            unsigned af[4][4], bf[4][2];
#pragma unroll
            for (int mt = 0; mt < 4; ++mt) {
                int r = wr * 64 + mt * 16 + gid;
                af[mt][0] = f2tf32(As[buf][r][kk + tig]);
                af[mt][1] = f2tf32(As[buf][r + 8][kk + tig]);
                af[mt][2] = f2tf32(As[buf][r][kk + tig + 4]);
                af[mt][3] = f2tf32(As[buf][r + 8][kk + tig + 4]);
            }
#pragma unroll
            for (int nt = 0; nt < 4; ++nt) {
                int rn = wc * 32 + nt * 8 + gid;
                bf[nt][0] = f2tf32(Bs[buf][rn][kk + tig]);
                bf[nt][1] = f2tf32(Bs[buf][rn][kk + tig + 4]);
            }
#pragma unroll
            for (int mt = 0; mt < 4; ++mt)
#pragma unroll
                for (int nt = 0; nt < 4; ++nt) mma_tf32(acc[mt][nt], af[mt], bf[nt]);
        }
        __syncthreads();
        buf ^= 1;
    }

    // ---------------- Epilogue ----------------
#pragma unroll
    for (int mt = 0; mt < 4; ++mt) {
        int row0 = m0 + wr * 64 + mt * 16 + gid;   // and row0+8
        int b0i = row0 >> 11, s0i = row0 & (S_ - 1);
        int row1 = row0 + 8;
        int b1i = row1 >> 11, s1i = row1 & (S_ - 1);

        float p0 = 0.f, p1 = 0.f;
        if (MODE == 2) {
            p0 = (float)pos[b0i * S_ + s0i];
            p1 = (float)pos[b1i * S_ + s1i];
        }

#pragma unroll
        for (int nt = 0; nt < 4; ++nt) {
            int col = n0 + wc * 32 + nt * 8 + 2 * tig;   // even column
            float e0 = acc[mt][nt][0], o0 = acc[mt][nt][1];
            float e1 = acc[mt][nt][2], o1 = acc[mt][nt][3];

            if (MODE == 2) {
                int j = (col & 63) >> 1;                  // pair index in head
                float freq = powf(10000.0f, -((float)(2 * j) / 64.0f));
                {
                    float ang = p0 * freq;
                    float cv = (float)cos((double)ang);
                    float sv = (float)sin((double)ang);
                    float re = e0 * cv - o0 * sv;
                    float ro = e0 * sv + o0 * cv;
                    e0 = re; o0 = ro;
                }
                {
                    float ang = p1 * freq;
                    float cv = (float)cos((double)ang);
                    float sv = (float)sin((double)ang);
                    float re = e1 * cv - o1 * sv;
                    float ro = e1 * sv + o1 * cv;
                    e1 = re; o1 = ro;
                }
            }

            if (MODE == 0) {
                *reinterpret_cast<float2*>(Cout + (size_t)row0 * D_ + col) =
                    make_float2(e0, o0);
                *reinterpret_cast<float2*>(Cout + (size_t)row1 * D_ + col) =
                    make_float2(e1, o1);
            } else {
                int h = col >> 6;
                int d = col & 63;
                *reinterpret_cast<float2*>(
                    Cout + (((size_t)(b0i * H_ + h) * S_ + s0i) * DK_ + d)) =
                    make_float2(e0, o0);
                *reinterpret_cast<float2*>(
                    Cout + (((size_t)(b1i * H_ + h) * S_ + s1i) * DK_ + d)) =
                    make_float2(e1, o1);
            }
        }
    }
}

// ---------------------------------------------------------------------------
// Flash attention, fp32, causal (unchanged from R0 — tf32 port next round).
// ---------------------------------------------------------------------------
#define FLASH_SMEM (3 * 64 * 68 * 4)

__global__ void __launch_bounds__(256) flash_kernel() {
    extern __shared__ float smf[];
    float(*Qts)[68] = reinterpret_cast<float(*)[68]>(smf);
    float(*KPs)[68] = reinterpret_cast<float(*)[68]>(smf + 64 * 68);
    float(*Vs)[68] = reinterpret_cast<float(*)[68]>(smf + 2 * 64 * 68);

    const int qb = blockIdx.x;
    const int bh = blockIdx.y;
    const int b = bh >> 4;
    const int h = bh & 15;

    const float* Qp = g_q + (size_t)bh * S_ * DK_;
    const float* Kp = g_k + (size_t)bh * S_ * DK_;
    const float* Vp = g_v + (size_t)bh * S_ * DK_;

    const int tid = threadIdx.x;
    const int tx = tid & 15;
    const int ty = tid >> 4;
    const int q0 = qb * 64;
    const float scale = 0.125f;

#pragma unroll
    for (int i = 0; i < 4; ++i) {
        int l = tid + i * 256;
        int r = l >> 4;
        int c = (l & 15) << 2;
        float4 v = *reinterpret_cast<const float4*>(Qp + (size_t)(q0 + r) * DK_ + c);
        Qts[c + 0][r] = v.x * scale;
        Qts[c + 1][r] = v.y * scale;
        Qts[c + 2][r] = v.z * scale;
        Qts[c + 3][r] = v.w * scale;
    }

    float m_i[4] = {-1e30f, -1e30f, -1e30f, -1e30f};
    float l_i[4] = {0.f, 0.f, 0.f, 0.f};
    float Oa[4][4];
#pragma unroll
    for (int i = 0; i < 4; ++i)
#pragma unroll
        for (int j = 0; j < 4; ++j) Oa[i][j] = 0.0f;

    for (int kb = 0; kb <= qb; ++kb) {
        const int k0 = kb * 64;
        __syncthreads();

#pragma unroll
        for (int i = 0; i < 4; ++i) {
            int l = tid + i * 256;
            int r = l >> 4;
            int c = (l & 15) << 2;
            float4 kv = *reinterpret_cast<const float4*>(Kp + (size_t)(k0 + r) * DK_ + c);
            KPs[c + 0][r] = kv.x; KPs[c + 1][r] = kv.y;
            KPs[c + 2][r] = kv.z; KPs[c + 3][r] = kv.w;
            float4 vv = *reinterpret_cast<const float4*>(Vp + (size_t)(k0 + r) * DK_ + c);
            *reinterpret_cast<float4*>(&Vs[r][c]) = vv;
        }
        __syncthreads();

        float sf[4][4];
#pragma unroll
        for (int i = 0; i < 4; ++i)
#pragma unroll
            for (int j = 0; j < 4; ++j) sf[i][j] = 0.0f;

#pragma unroll 8
        for (int kk = 0; kk < 64; ++kk) {
            float4 a4 = *reinterpret_cast<const float4*>(&Qts[kk][ty * 4]);
            float4 b4 = *reinterpret_cast<const float4*>(&KPs[kk][tx * 4]);
            float qv[4] = {a4.x, a4.y, a4.z, a4.w};
            float kv[4] = {b4.x, b4.y, b4.z, b4.w};
#pragma unroll
            for (int i = 0; i < 4; ++i)
#pragma unroll
                for (int j = 0; j < 4; ++j) sf[i][j] = fmaf(qv[i], kv[j], sf[i][j]);
        }

        if (kb == qb) {
#pragma unroll
            for (int i = 0; i < 4; ++i)
#pragma unroll
                for (int j = 0; j < 4; ++j)
                    if (tx * 4 + j > ty * 4 + i) sf[i][j] = -1e30f;
        }

#pragma unroll
        for (int i = 0; i < 4; ++i) {
            float mx = fmaxf(fmaxf(sf[i][0], sf[i][1]), fmaxf(sf[i][2], sf[i][3]));
#pragma unroll
            for (int off = 8; off > 0; off >>= 1)
                mx = fmaxf(mx, __shfl_xor_sync(0xffffffffu, mx, off));
            float mn = fmaxf(m_i[i], mx);
            float alpha = expf(m_i[i] - mn);
            float ps = 0.0f;
#pragma unroll
            for (int j = 0; j < 4; ++j) {
                float pp = expf(sf[i][j] - mn);
                sf[i][j] = pp;
                ps += pp;
            }
#pragma unroll
            for (int off = 8; off > 0; off >>= 1)
                ps += __shfl_xor_sync(0xffffffffu, ps, off);
            l_i[i] = l_i[i] * alpha + ps;
            m_i[i] = mn;
#pragma unroll
            for (int j = 0; j < 4; ++j) Oa[i][j] *= alpha;
        }

        __syncthreads();
#pragma unroll
        for (int i = 0; i < 4; ++i)
            *reinterpret_cast<float4*>(&KPs[ty * 4 + i][tx * 4]) =
                make_float4(sf[i][0], sf[i][1], sf[i][2], sf[i][3]);
        __syncthreads();

#pragma unroll 8
        for (int kk = 0; kk < 64; ++kk) {
            float4 b4 = *reinterpret_cast<const float4*>(&Vs[kk][tx * 4]);
            float vv[4] = {b4.x, b4.y, b4.z, b4.w};
            float pv[4];
#pragma unroll
            for (int i = 0; i < 4; ++i) pv[i] = KPs[ty * 4 + i][kk];
#pragma unroll
            for (int i = 0; i < 4; ++i)
#pragma unroll
                for (int j = 0; j < 4; ++j) Oa[i][j] = fmaf(pv[i], vv[j], Oa[i][j]);
        }
    }

#pragma unroll
    for (int i = 0; i < 4; ++i) {
        float inv = 1.0f / l_i[i];
        int r = q0 + ty * 4 + i;
        float4 o = make_float4(Oa[i][0] * inv, Oa[i][1] * inv, Oa[i][2] * inv,
                               Oa[i][3] * inv);
        *reinterpret_cast<float4*>(
            &g_attn[((size_t)(b * S_ + r)) * D_ + h * DK_ + tx * 4]) = o;
    }
}

// ---------------------------------------------------------------------------
extern "C" void kernel_launch(void* const* d_in, const int* in_sizes, int n_in,
                              void* d_out, int out_size) {
    const float* x = (const float*)d_in[0];
    const int* pos = (const int*)d_in[1];
    const float* wq = (const float*)d_in[2];
    const float* wk = (const float*)d_in[3];
    const float* wv = (const float*)d_in[4];
    const float* wo = (const float*)d_in[5];
    float* out = (float*)d_out;

    float *qp, *kp, *vp, *attnp;
    cudaGetSymbolAddress((void**)&qp, g_q);
    cudaGetSymbolAddress((void**)&kp, g_k);
    cudaGetSymbolAddress((void**)&vp, g_v);
    cudaGetSymbolAddress((void**)&attnp, g_attn);

    static bool attr_done = false;
    if (!attr_done) {
        cudaFuncSetAttribute(gemm_tf32_kernel<0>,
                             cudaFuncAttributeMaxDynamicSharedMemorySize, GEMM_SMEM);
        cudaFuncSetAttribute(gemm_tf32_kernel<1>,
                             cudaFuncAttributeMaxDynamicSharedMemorySize, GEMM_SMEM);
        cudaFuncSetAttribute(gemm_tf32_kernel<2>,
                             cudaFuncAttributeMaxDynamicSharedMemorySize, GEMM_SMEM);
        cudaFuncSetAttribute(flash_kernel,
                             cudaFuncAttributeMaxDynamicSharedMemorySize, FLASH_SMEM);
        attr_done = true;
    }

    dim3 gemm_grid(D_ / 128, M_ / 128);   // (8, 32)
    gemm_tf32_kernel<2><<<gemm_grid, 256, GEMM_SMEM>>>(x, wq, qp, pos);
    gemm_tf32_kernel<2><<<gemm_grid, 256, GEMM_SMEM>>>(x, wk, kp, pos);
    gemm_tf32_kernel<1><<<gemm_grid, 256, GEMM_SMEM>>>(x, wv, vp, pos);

    dim3 flash_grid(S_ / 64, B_ * H_);    // (32, 32)
    flash_kernel<<<flash_grid, 256, FLASH_SMEM>>>();

    gemm_tf32_kernel<0><<<gemm_grid, 256, GEMM_SMEM>>>(attnp, wo, out, pos);
}

// round 3
// speedup vs baseline: 3.2098x; 1.8788x over previous
#include <cuda_runtime.h>
#include <math.h>

// Problem constants (fixed by the reference).
#define B_ 2
#define S_ 2048
#define D_ 1024
#define H_ 16
#define DK_ 64
#define M_ (B_ * S_)   // 4096 token rows

// Scratch (allocation-free rule: __device__ globals).
__device__ float g_q[B_ * H_ * S_ * DK_];     // [b,h,s,d]
__device__ float g_k[B_ * H_ * S_ * DK_];
__device__ float g_v[B_ * H_ * S_ * DK_];
__device__ float g_attn[M_ * D_];             // [b,s,h*dk]

// ---------------------------------------------------------------------------
// tf32 / cp.async helpers
// ---------------------------------------------------------------------------
__device__ __forceinline__ unsigned f2tf32(float f) {
    unsigned u;
    asm("cvt.rna.tf32.f32 %0, %1;" : "=r"(u) : "f"(f));
    return u;
}

__device__ __forceinline__ void mma_tf32(float (&c)[4], const unsigned (&a)[4],
                                         const unsigned (&b)[2]) {
    asm volatile(
        "mma.sync.aligned.m16n8k8.row.col.f32.tf32.tf32.f32 "
        "{%0,%1,%2,%3}, {%4,%5,%6,%7}, {%8,%9}, {%0,%1,%2,%3};\n"
        : "+f"(c[0]), "+f"(c[1]), "+f"(c[2]), "+f"(c[3])
        : "r"(a[0]), "r"(a[1]), "r"(a[2]), "r"(a[3]), "r"(b[0]), "r"(b[1]));
}

__device__ __forceinline__ void cp_async16(void* smem, const void* gmem) {
    unsigned saddr = (unsigned)__cvta_generic_to_shared(smem);
    asm volatile("cp.async.cg.shared.global [%0], [%1], 16;\n" ::"r"(saddr),
                 "l"(gmem));
}
__device__ __forceinline__ void cp_commit() {
    asm volatile("cp.async.commit_group;\n");
}
template <int N>
__device__ __forceinline__ void cp_wait() {
    asm volatile("cp.async.wait_group %0;\n" ::"n"(N));
}

// ---------------------------------------------------------------------------
// tf32 GEMM (NT): C[m,n] = sum_k A[m,k] * W[n,k]. (unchanged from R1)
// MODE 0: plain, MODE 1: [b,h,s,d] scatter, MODE 2: scatter + fused RoPE
// ---------------------------------------------------------------------------
#define GSTRIDE 36
#define GEMM_SMEM (2 * 2 * 128 * GSTRIDE * 4)

template <int MODE>
__global__ void __launch_bounds__(256) gemm_tf32_kernel(
    const float* __restrict__ A, const float* __restrict__ W,
    float* __restrict__ Cout, const int* __restrict__ pos) {
    extern __shared__ float sm[];
    float(*As)[128][GSTRIDE] = reinterpret_cast<float(*)[128][GSTRIDE]>(sm);
    float(*Bs)[128][GSTRIDE] =
        reinterpret_cast<float(*)[128][GSTRIDE]>(sm + 2 * 128 * GSTRIDE);

    const int tid = threadIdx.x;
    const int lane = tid & 31;
    const int warp = tid >> 5;
    const int wr = warp >> 2;
    const int wc = warp & 3;
    const int m0 = blockIdx.y * 128;
    const int n0 = blockIdx.x * 128;
    const int gid = lane >> 2;
    const int tig = lane & 3;

    const float* Ab = A + (size_t)m0 * D_;
    const float* Wb = W + (size_t)n0 * D_;

    float acc[4][4][4];
#pragma unroll
    for (int i = 0; i < 4; ++i)
#pragma unroll
        for (int j = 0; j < 4; ++j)
#pragma unroll
            for (int r = 0; r < 4; ++r) acc[i][j][r] = 0.0f;

    auto issue = [&](int buf, int k0) {
#pragma unroll
        for (int i = 0; i < 4; ++i) {
            int l = tid + i * 256;
            int r = l >> 3;
            int c = (l & 7) << 2;
            cp_async16(&As[buf][r][c], Ab + (size_t)r * D_ + k0 + c);
            cp_async16(&Bs[buf][r][c], Wb + (size_t)r * D_ + k0 + c);
        }
        cp_commit();
    };

    const int NIT = D_ / 32;
    issue(0, 0);
    int buf = 0;
    for (int it = 0; it < NIT; ++it) {
        if (it + 1 < NIT) {
            issue(buf ^ 1, (it + 1) * 32);
            cp_wait<1>();
        } else {
            cp_wait<0>();
        }
        __syncthreads();

#pragma unroll
        for (int kk = 0; kk < 32; kk += 8) {
            unsigned af[4][4], bf[4][2];
#pragma unroll
            for (int mt = 0; mt < 4; ++mt) {
                int r = wr * 64 + mt * 16 + gid;
                af[mt][0] = f2tf32(As[buf][r][kk + tig]);
                af[mt][1] = f2tf32(As[buf][r + 8][kk + tig]);
                af[mt][2] = f2tf32(As[buf][r][kk + tig + 4]);
                af[mt][3] = f2tf32(As[buf][r + 8][kk + tig + 4]);
            }
#pragma unroll
            for (int nt = 0; nt < 4; ++nt) {
                int rn = wc * 32 + nt * 8 + gid;
                bf[nt][0] = f2tf32(Bs[buf][rn][kk + tig]);
                bf[nt][1] = f2tf32(Bs[buf][rn][kk + tig + 4]);
            }
#pragma unroll
            for (int mt = 0; mt < 4; ++mt)
#pragma unroll
                for (int nt = 0; nt < 4; ++nt) mma_tf32(acc[mt][nt], af[mt], bf[nt]);
        }
        __syncthreads();
        buf ^= 1;
    }

#pragma unroll
    for (int mt = 0; mt < 4; ++mt) {
        int row0 = m0 + wr * 64 + mt * 16 + gid;
        int b0i = row0 >> 11, s0i = row0 & (S_ - 1);
        int row1 = row0 + 8;
        int b1i = row1 >> 11, s1i = row1 & (S_ - 1);

        float p0 = 0.f, p1 = 0.f;
        if (MODE == 2) {
            p0 = (float)pos[b0i * S_ + s0i];
            p1 = (float)pos[b1i * S_ + s1i];
        }

#pragma unroll
        for (int nt = 0; nt < 4; ++nt) {
            int col = n0 + wc * 32 + nt * 8 + 2 * tig;
            float e0 = acc[mt][nt][0], o0 = acc[mt][nt][1];
            float e1 = acc[mt][nt][2], o1 = acc[mt][nt][3];

            if (MODE == 2) {
                int j = (col & 63) >> 1;
                float freq = powf(10000.0f, -((float)(2 * j) / 64.0f));
                {
                    float ang = p0 * freq;
                    float cv = (float)cos((double)ang);
                    float sv = (float)sin((double)ang);
                    float re = e0 * cv - o0 * sv;
                    float ro = e0 * sv + o0 * cv;
                    e0 = re; o0 = ro;
                }
                {
                    float ang = p1 * freq;
                    float cv = (float)cos((double)ang);
                    float sv = (float)sin((double)ang);
                    float re = e1 * cv - o1 * sv;
                    float ro = e1 * sv + o1 * cv;
                    e1 = re; o1 = ro;
                }
            }

            if (MODE == 0) {
                *reinterpret_cast<float2*>(Cout + (size_t)row0 * D_ + col) =
                    make_float2(e0, o0);
                *reinterpret_cast<float2*>(Cout + (size_t)row1 * D_ + col) =
                    make_float2(e1, o1);
            } else {
                int h = col >> 6;
                int d = col & 63;
                *reinterpret_cast<float2*>(
                    Cout + (((size_t)(b0i * H_ + h) * S_ + s0i) * DK_ + d)) =
                    make_float2(e0, o0);
                *reinterpret_cast<float2*>(
                    Cout + (((size_t)(b1i * H_ + h) * S_ + s1i) * DK_ + d)) =
                    make_float2(e1, o1);
            }
        }
    }
}

// ---------------------------------------------------------------------------
// Flash attention, tf32 tensor cores, causal.
// BM=128 q-rows/CTA, BN=64 keys/iter, dk=64. 256 threads = 8 warps,
// each warp owns 16 q-rows (full 64-col accumulation).
// Smem (floats):
//   Qs[128][68]        Q tile (pre-scaled), row-major
//   Ks[2][64][68]      K tiles (raw, cp.async double-buffered), row-major [n][d]
//   Vs[2][64][72]      V tiles (raw, cp.async),                  row-major [k][d]
//   Ps[128][68]        P tile (warp-private row slabs)
// tf32 conversion happens at fragment load (matches R1 GEMM pattern).
// Pitch 68 -> conflict-free 8x4 row pattern; pitch 72 -> conflict-free 4x8
// transposed pattern for V's B-fragments.
// ---------------------------------------------------------------------------
#define FP 68
#define VP 72
#define FLASH_SMEM ((128 * FP + 2 * 64 * FP + 2 * 64 * VP + 128 * FP) * 4)

__global__ void __launch_bounds__(256) flash_tf32_kernel() {
    extern __shared__ float smf[];
    float* Qs = smf;                            // [128][FP]
    float* Ks = Qs + 128 * FP;                  // [2][64][FP]
    float* Vs = Ks + 2 * 64 * FP;               // [2][64][VP]
    float* Ps = Vs + 2 * 64 * VP;               // [128][FP]

    const int qb = gridDim.x - 1 - blockIdx.x;  // long blocks first
    const int bh = blockIdx.y;
    const int b = bh >> 4;
    const int h = bh & 15;

    const float* Qp = g_q + (size_t)bh * S_ * DK_;
    const float* Kp = g_k + (size_t)bh * S_ * DK_;
    const float* Vp = g_v + (size_t)bh * S_ * DK_;

    const int tid = threadIdx.x;
    const int lane = tid & 31;
    const int warp = tid >> 5;
    const int gid = lane >> 2;
    const int tig = lane & 3;
    const int q0 = qb * 128;
    const int mrow = warp * 16 + gid;           // warp-local base row in tile

    // Load Q tile, scaled by 1/sqrt(dk)=0.125.
#pragma unroll
    for (int i = 0; i < 8; ++i) {
        int l = tid + i * 256;
        int r = l >> 4;
        int c = (l & 15) << 2;
        float4 v = *reinterpret_cast<const float4*>(Qp + (size_t)(q0 + r) * DK_ + c);
        Qs[r * FP + c + 0] = v.x * 0.125f;
        Qs[r * FP + c + 1] = v.y * 0.125f;
        Qs[r * FP + c + 2] = v.z * 0.125f;
        Qs[r * FP + c + 3] = v.w * 0.125f;
    }

    auto issueKV = [&](int bf, int k0) {
#pragma unroll
        for (int i = 0; i < 4; ++i) {
            int l = tid + i * 256;
            int r = l >> 4;
            int c = (l & 15) << 2;
            cp_async16(Ks + bf * 64 * FP + r * FP + c,
                       Kp + (size_t)(k0 + r) * DK_ + c);
            cp_async16(Vs + bf * 64 * VP + r * VP + c,
                       Vp + (size_t)(k0 + r) * DK_ + c);
        }
        cp_commit();
    };

    issueKV(0, 0);

    float m_i[2] = {-1e30f, -1e30f};
    float l_i[2] = {0.f, 0.f};
    float Oacc[8][4];
#pragma unroll
    for (int nt = 0; nt < 8; ++nt)
#pragma unroll
        for (int r = 0; r < 4; ++r) Oacc[nt][r] = 0.0f;

    const int ntiles = 2 * qb + 2;
    int buf = 0;
    for (int kb = 0; kb < ntiles; ++kb) {
        const int k0 = kb * 64;
        cp_wait<0>();
        __syncthreads();                        // tile ready; all warps past reads
        if (kb + 1 < ntiles) issueKV(buf ^ 1, k0 + 64);

        // ---- S = Q K^T ----
        const float* Kb = Ks + buf * 64 * FP;
        float Sacc[8][4];
#pragma unroll
        for (int nt = 0; nt < 8; ++nt)
#pragma unroll
            for (int r = 0; r < 4; ++r) Sacc[nt][r] = 0.0f;

#pragma unroll
        for (int kk = 0; kk < 64; kk += 8) {
            unsigned af[4];
            af[0] = f2tf32(Qs[(mrow) * FP + kk + tig]);
            af[1] = f2tf32(Qs[(mrow + 8) * FP + kk + tig]);
            af[2] = f2tf32(Qs[(mrow) * FP + kk + tig + 4]);
            af[3] = f2tf32(Qs[(mrow + 8) * FP + kk + tig + 4]);
#pragma unroll
            for (int nt = 0; nt < 8; ++nt) {
                unsigned bf[2];
                bf[0] = f2tf32(Kb[(nt * 8 + gid) * FP + kk + tig]);
                bf[1] = f2tf32(Kb[(nt * 8 + gid) * FP + kk + tig + 4]);
                mma_tf32(Sacc[nt], af, bf);
            }
        }

        // ---- causal mask ----
        const int row0 = q0 + mrow;
        const int row1 = row0 + 8;
        if (k0 + 63 > row0) {
#pragma unroll
            for (int nt = 0; nt < 8; ++nt) {
                int c0 = k0 + nt * 8 + 2 * tig;
                if (c0 > row0) Sacc[nt][0] = -1e30f;
                if (c0 + 1 > row0) Sacc[nt][1] = -1e30f;
                if (c0 > row1) Sacc[nt][2] = -1e30f;
                if (c0 + 1 > row1) Sacc[nt][3] = -1e30f;
            }
        }

        // ---- online softmax ----
        float mx0 = -1e30f, mx1 = -1e30f;
#pragma unroll
        for (int nt = 0; nt < 8; ++nt) {
            mx0 = fmaxf(mx0, fmaxf(Sacc[nt][0], Sacc[nt][1]));
            mx1 = fmaxf(mx1, fmaxf(Sacc[nt][2], Sacc[nt][3]));
        }
        mx0 = fmaxf(mx0, __shfl_xor_sync(0xffffffffu, mx0, 1));
        mx0 = fmaxf(mx0, __shfl_xor_sync(0xffffffffu, mx0, 2));
        mx1 = fmaxf(mx1, __shfl_xor_sync(0xffffffffu, mx1, 1));
        mx1 = fmaxf(mx1, __shfl_xor_sync(0xffffffffu, mx1, 2));

        float mn0 = fmaxf(m_i[0], mx0);
        float mn1 = fmaxf(m_i[1], mx1);
        float a0 = __expf(m_i[0] - mn0);
        float a1 = __expf(m_i[1] - mn1);

        float ps0 = 0.f, ps1 = 0.f;
#pragma unroll
        for (int nt = 0; nt < 8; ++nt) {
            float p00 = __expf(Sacc[nt][0] - mn0);
            float p01 = __expf(Sacc[nt][1] - mn0);
            float p10 = __expf(Sacc[nt][2] - mn1);
            float p11 = __expf(Sacc[nt][3] - mn1);
            ps0 += p00 + p01;
            ps1 += p10 + p11;
            *reinterpret_cast<float2*>(&Ps[(mrow) * FP + nt * 8 + 2 * tig]) =
                make_float2(p00, p01);
            *reinterpret_cast<float2*>(&Ps[(mrow + 8) * FP + nt * 8 + 2 * tig]) =
                make_float2(p10, p11);
        }
        ps0 += __shfl_xor_sync(0xffffffffu, ps0, 1);
        ps0 += __shfl_xor_sync(0xffffffffu, ps0, 2);
        ps1 += __shfl_xor_sync(0xffffffffu, ps1, 1);
        ps1 += __shfl_xor_sync(0xffffffffu, ps1, 2);

        l_i[0] = l_i[0] * a0 + ps0;
        l_i[1] = l_i[1] * a1 + ps1;
        m_i[0] = mn0;
        m_i[1] = mn1;
#pragma unroll
        for (int nt = 0; nt < 8; ++nt) {
            Oacc[nt][0] *= a0;
            Oacc[nt][1] *= a0;
            Oacc[nt][2] *= a1;
            Oacc[nt][3] *= a1;
        }
        __syncwarp();   // P rows are warp-private; warp-level visibility enough

        // ---- O += P V ----
        const float* Vb = Vs + buf * 64 * VP;
#pragma unroll
        for (int kk = 0; kk < 64; kk += 8) {
            unsigned af[4];
            af[0] = f2tf32(Ps[(mrow) * FP + kk + tig]);
            af[1] = f2tf32(Ps[(mrow + 8) * FP + kk + tig]);
            af[2] = f2tf32(Ps[(mrow) * FP + kk + tig + 4]);
            af[3] = f2tf32(Ps[(mrow + 8) * FP + kk + tig + 4]);
#pragma unroll
            for (int nt = 0; nt < 8; ++nt) {
                unsigned bf[2];
                bf[0] = f2tf32(Vb[(kk + tig) * VP + nt * 8 + gid]);
                bf[1] = f2tf32(Vb[(kk + tig + 4) * VP + nt * 8 + gid]);
                mma_tf32(Oacc[nt], af, bf);
            }
        }
        buf ^= 1;
    }

    // ---- normalize + write to token-major g_attn ----
    float inv0 = 1.0f / l_i[0];
    float inv1 = 1.0f / l_i[1];
    const int row0 = q0 + mrow;
    const int row1 = row0 + 8;
#pragma unroll
    for (int nt = 0; nt < 8; ++nt) {
        int col = h * DK_ + nt * 8 + 2 * tig;
        *reinterpret_cast<float2*>(&g_attn[((size_t)(b * S_ + row0)) * D_ + col]) =
            make_float2(Oacc[nt][0] * inv0, Oacc[nt][1] * inv0);
        *reinterpret_cast<float2*>(&g_attn[((size_t)(b * S_ + row1)) * D_ + col]) =
            make_float2(Oacc[nt][2] * inv1, Oacc[nt][3] * inv1);
    }
}

// ---------------------------------------------------------------------------
extern "C" void kernel_launch(void* const* d_in, const int* in_sizes, int n_in,
                              void* d_out, int out_size) {
    const float* x = (const float*)d_in[0];
    const int* pos = (const int*)d_in[1];
    const float* wq = (const float*)d_in[2];
    const float* wk = (const float*)d_in[3];
    const float* wv = (const float*)d_in[4];
    const float* wo = (const float*)d_in[5];
    float* out = (float*)d_out;

    float *qp, *kp, *vp, *attnp;
    cudaGetSymbolAddress((void**)&qp, g_q);
    cudaGetSymbolAddress((void**)&kp, g_k);
    cudaGetSymbolAddress((void**)&vp, g_v);
    cudaGetSymbolAddress((void**)&attnp, g_attn);

    static bool attr_done = false;
    if (!attr_done) {
        cudaFuncSetAttribute(gemm_tf32_kernel<0>,
                             cudaFuncAttributeMaxDynamicSharedMemorySize, GEMM_SMEM);
        cudaFuncSetAttribute(gemm_tf32_kernel<1>,
                             cudaFuncAttributeMaxDynamicSharedMemorySize, GEMM_SMEM);
        cudaFuncSetAttribute(gemm_tf32_kernel<2>,
                             cudaFuncAttributeMaxDynamicSharedMemorySize, GEMM_SMEM);
        cudaFuncSetAttribute(flash_tf32_kernel,
                             cudaFuncAttributeMaxDynamicSharedMemorySize, FLASH_SMEM);
        attr_done = true;
    }

    dim3 gemm_grid(D_ / 128, M_ / 128);   // (8, 32)
    gemm_tf32_kernel<2><<<gemm_grid, 256, GEMM_SMEM>>>(x, wq, qp, pos);
    gemm_tf32_kernel<2><<<gemm_grid, 256, GEMM_SMEM>>>(x, wk, kp, pos);
    gemm_tf32_kernel<1><<<gemm_grid, 256, GEMM_SMEM>>>(x, wv, vp, pos);

    dim3 flash_grid(S_ / 128, B_ * H_);   // (16, 32)
    flash_tf32_kernel<<<flash_grid, 256, FLASH_SMEM>>>();

    gemm_tf32_kernel<0><<<gemm_grid, 256, GEMM_SMEM>>>(attnp, wo, out, pos);
}